// round 8
// baseline (speedup 1.0000x reference)
#include <cuda_runtime.h>
#include <cstdint>

#define B_SZ  8
#define SEQ   4096
#define HID   1024
#define NGRP  (SEQ / 32)     // 128 t-groups of 32 steps
#define DMAX  64             // FIR truncation: g[d] ~ 0.16^d
#define CHUNKS 8             // time-chunks for the SNN scan
#define CGRP   (NGRP / CHUNKS)  // 16 stored groups per chunk
#define WGRP   8             // warmup groups (256 steps): 0.9^256 ~ 2e-12
#define YC     256           // t-chunk per fused u+y block
#define PF     16            // prefetch ring depth (steps)

// ---------------- scratch (device globals; no allocation allowed) ----------------
// bit (t&31) of word [b][t>>5][h] = spike(b,t,h). 4 MB.
__device__ unsigned g_bits[B_SZ][NGRP][HID];
__device__ float    g_g[DMAX];          // impulse response C A^d B
__device__ float    g_y[B_SZ][SEQ];     // y[b][t]

// ---------------- LIF step: float-mask form (masks exactly 0.0/1.0) --------------
// w09 = rn(0.9 * v_pre-reset), ns = 1-spike_prev, act = (r<=0), r exact int.
// Every FFMA multiplies by exact 0/1 so rounding == reference's mul+add.
struct SnnState { float w09, ns, act, r; };

__device__ __forceinline__ void snn_step(SnnState& st, float xk,
                                         float& macc, float mc)
{
    float v1 = __fmaf_rn(st.w09, st.ns, xk);          // rn(0.9*v_post + x)
    float ge; asm("set.ge.f32.f32 %0, %1, %2;" : "=f"(ge) : "f"(v1), "f"(1.0f));
    float s  = __fmul_rn(ge, st.act);                 // spike as 0.0/1.0
    st.w09   = __fmul_rn(v1, 0.9f);
    st.ns    = __fmaf_rn(-ge, st.act, 1.0f);          // 1 - spike (exact)
    float rd = fmaxf(__fadd_rn(st.r, -1.0f), 0.0f);   // max(r-1,0), exact
    st.r     = __fmaf_rn(s, 5.0f, rd);                // spike => rd==0 => 5
    asm("set.le.f32.f32 %0, %1, %2;" : "=f"(st.act) : "f"(st.r), "f"(0.0f));
    macc     = __fmaf_rn(s, mc, macc);                // exact bit accumulation
}

// ---------------- pass 1: LIF neurons -> spike bitmasks (+hidden g block) --------
// 128 snn blocks of 128 threads: (b, hhalf, chunk); each thread runs FOUR
// adjacent (b,h) lanes (float4 loads, 4 independent chains = in-warp ILP).
// Last block computes g[d] = C A^d B concurrently.
__global__ void __launch_bounds__(128) snn_kernel(const float* __restrict__ x,
                                                  const float* __restrict__ Ap,
                                                  const float* __restrict__ Bp,
                                                  const float* __restrict__ Cp)
{
    __shared__ float As[64 * 65];
    __shared__ float ws[64];
    __shared__ float red[2];

    if (blockIdx.x >= B_SZ * 2 * CHUNKS) {
        // ---- g block: g[d] = C . (A^d B), d = 0..63 (tid<64 active) ----
        const int tid = threadIdx.x;
        for (int i = tid; i < 64 * 64; i += 128)
            As[(i >> 6) * 65 + (i & 63)] = Ap[i];
        float cv = 0.f, w = 0.f;
        if (tid < 64) { cv = Cp[tid]; w = Bp[tid]; ws[tid] = w; }
        __syncthreads();
        for (int d = 0; d < DMAX; d++) {
            if (tid < 64) {
                float p = cv * w;
                #pragma unroll
                for (int o = 16; o; o >>= 1) p += __shfl_down_sync(0xffffffffu, p, o);
                if ((tid & 31) == 0) red[tid >> 5] = p;
            }
            __syncthreads();
            if (tid == 0) g_g[d] = red[0] + red[1];
            if (d < DMAX - 1) {
                float wn = 0.f;
                if (tid < 64) {
                    float a0 = 0.f, a1 = 0.f, a2 = 0.f, a3 = 0.f;
                    #pragma unroll
                    for (int s = 0; s < 64; s += 4) {
                        a0 += As[tid * 65 + s + 0] * ws[s + 0];
                        a1 += As[tid * 65 + s + 1] * ws[s + 1];
                        a2 += As[tid * 65 + s + 2] * ws[s + 2];
                        a3 += As[tid * 65 + s + 3] * ws[s + 3];
                    }
                    wn = (a0 + a1) + (a2 + a3);
                }
                __syncthreads();
                if (tid < 64) ws[tid] = wn;
                __syncthreads();
                w = wn;
            }
        }
        return;
    }

    // ---- SNN path: 4 lanes per thread ----
    const int blk   = blockIdx.x;              // 0..127
    const int c     = blk & (CHUNKS - 1);
    const int hhalf = (blk >> 3) & 1;
    const int b     = blk >> 4;
    const int tid   = threadIdx.x;
    const int h     = hhalf * 512 + tid * 4;   // 4 consecutive hidden units

    const int warm    = (c == 0) ? 0 : WGRP;
    const int g0      = c * CGRP;
    const int tbegin  = g0 * 32 - warm * 32;
    const int ngroups = warm + CGRP;           // 16 or 24

    const float4* xp = (const float4*)(x + ((size_t)b * SEQ + tbegin) * HID + h);
    uint4* sbw = (uint4*)&g_bits[b][g0][h];
    const int HID4 = HID / 4;

    // PF-deep float4 ring; all indices (i & 15) compile-constant when unrolled.
    float4 buf[PF];
    #pragma unroll
    for (int i = 0; i < PF; i++) buf[i] = xp[(size_t)i * HID4];

    SnnState s0 = {0,1,1,0}, s1 = {0,1,1,0}, s2 = {0,1,1,0}, s3 = {0,1,1,0};

    for (int gg = 0; gg < ngroups; gg++) {
        const float4* xpf = xp + ((size_t)gg * 32 + PF) * HID4;  // t+PF for i=0
        const bool pfh = (gg + 1 < ngroups);   // prefetch valid for i>=16
        float m0l=0,m0h=0, m1l=0,m1h=0, m2l=0,m2h=0, m3l=0,m3h=0;

        #pragma unroll
        for (int i = 0; i < 32; i++) {
            float4 xk = buf[i & (PF - 1)];
            if (i < 32 - PF || pfh)
                buf[i & (PF - 1)] = xpf[(size_t)i * HID4];  // prefetch t+PF
            const float mc = (float)(1u << (i & 15));
            if (i < 16) {
                snn_step(s0, xk.x, m0l, mc);
                snn_step(s1, xk.y, m1l, mc);
                snn_step(s2, xk.z, m2l, mc);
                snn_step(s3, xk.w, m3l, mc);
            } else {
                snn_step(s0, xk.x, m0h, mc);
                snn_step(s1, xk.y, m1h, mc);
                snn_step(s2, xk.z, m2h, mc);
                snn_step(s3, xk.w, m3h, mc);
            }
        }
        if (gg >= warm) {
            uint4 mv;
            mv.x = __float2uint_rn(m0l) | (__float2uint_rn(m0h) << 16);
            mv.y = __float2uint_rn(m1l) | (__float2uint_rn(m1h) << 16);
            mv.z = __float2uint_rn(m2l) | (__float2uint_rn(m2h) << 16);
            mv.w = __float2uint_rn(m3l) | (__float2uint_rn(m3h) << 16);
            *sbw = mv;                          // coalesced 16B store
            sbw += HID4;
        }
    }
}

// ---------------- pass 2: fused u (popcount transpose) + y (64-tap FIR) ----------
// grid: B_SZ*16 blocks, 256 threads; block (b,yc) produces y[b][yc*256 .. +256).
__global__ void __launch_bounds__(256) uy_kernel(const float* __restrict__ Dp)
{
    __shared__ unsigned wsm[HID];
    __shared__ int   part[8 * 32];
    __shared__ float u_s[64 + YC];   // u_s[i] = u[t0 - 64 + i]
    __shared__ float g_s[DMAX];

    const int b   = blockIdx.x >> 4;
    const int yc  = blockIdx.x & 15;
    const int t0  = yc * YC;
    const int gb  = yc * (YC / 32);
    const int tid = threadIdx.x;
    const int wid = tid >> 5, lane = tid & 31;

    if (tid < DMAX) g_s[tid] = g_g[tid];

    for (int j = -2; j < YC / 32; j++) {        // 2 halo groups + 8 own groups
        const int g  = gb + j;
        const int i0 = 64 + j * 32;
        if (g < 0) {
            if (tid < 32) u_s[i0 + tid] = 0.0f;
            continue;
        }
        ((uint4*)wsm)[tid] = ((const uint4*)&g_bits[b][g][0])[tid];
        __syncthreads();
        int cnt = 0;
        #pragma unroll 8
        for (int i2 = 0; i2 < 128; i2++)
            cnt += (int)((wsm[wid * 128 + i2] >> lane) & 1u);
        part[wid * 32 + lane] = cnt;
        __syncthreads();
        if (tid < 32) {
            int tot = 0;
            #pragma unroll
            for (int ww = 0; ww < 8; ww++) tot += part[ww * 32 + tid];
            u_s[i0 + tid] = (float)tot * (1.0f / (float)HID);
        }
        __syncthreads();
    }

    const float Ds = *Dp;
    {
        const int i = tid;                      // YC == blockDim.x
        float acc = Ds * u_s[64 + i];
        #pragma unroll
        for (int d = 0; d < DMAX; d++)
            acc += g_s[d] * u_s[64 + i - d];
        g_y[b][t0 + i] = acc;
    }
}

// ---------------- pass 3: out[b][t][h] = spike_bit + y[b][t] ---------------------
// grid: B_SZ * NGRP * 2 blocks; block covers 16 t x 1024 h (64 KB of output).
__global__ void __launch_bounds__(256) out_kernel(float4* __restrict__ out)
{
    __shared__ float ys[16], ys1[16];

    const int blk  = blockIdx.x;
    const int half = blk & 1;
    const int g    = (blk >> 1) & (NGRP - 1);
    const int b    = blk >> 8;
    const int tid  = threadIdx.x;            // h4 = tid: hidden 4*tid..4*tid+3

    if (tid < 16) {
        float yv = g_y[b][g * 32 + half * 16 + tid];
        ys[tid]  = yv;
        ys1[tid] = yv + 1.0f;
    }
    const uint4 wv = ((const uint4*)&g_bits[b][g][0])[tid];
    __syncthreads();

    float4* base = out + ((size_t)(b * SEQ + g * 32 + half * 16) * HID) / 4 + tid;
    #pragma unroll
    for (int t = 0; t < 16; t++) {
        const unsigned bit = 1u << (half * 16 + t);
        const float y  = ys[t];
        const float y1 = ys1[t];
        float4 o;
        o.x = (wv.x & bit) ? y1 : y;
        o.y = (wv.y & bit) ? y1 : y;
        o.z = (wv.z & bit) ? y1 : y;
        o.w = (wv.w & bit) ? y1 : y;
        __stcs(&base[(size_t)t * (HID / 4)], o);
    }
}

// ---------------- launch ----------------------------------------------------------
extern "C" void kernel_launch(void* const* d_in, const int* in_sizes, int n_in,
                              void* d_out, int out_size)
{
    const float* x  = (const float*)d_in[0];   // (8, 4096, 1024) f32
    const float* A  = (const float*)d_in[1];   // (64, 64)
    const float* Bv = (const float*)d_in[2];   // (64, 1)
    const float* Cv = (const float*)d_in[3];   // (1, 64)
    const float* Dp = (const float*)d_in[4];   // (1, 1)

    snn_kernel<<<B_SZ * 2 * CHUNKS + 1, 128>>>(x, A, Bv, Cv);
    uy_kernel<<<B_SZ * 16, 256>>>(Dp);
    out_kernel<<<B_SZ * NGRP * 2, 256>>>((float4*)d_out);
}

// round 9
// speedup vs baseline: 1.2887x; 1.2887x over previous
#include <cuda_runtime.h>
#include <cstdint>

#define B_SZ  8
#define SEQ   4096
#define HID   1024
#define NGRP  (SEQ / 32)     // 128 t-groups of 32 steps
#define DMAX  64             // FIR truncation: g[d] ~ 0.16^d
#define CHUNKS 8             // time-chunks for the SNN scan
#define CGRP   (NGRP / CHUNKS)  // 16 stored groups per chunk
#define WGRP   8             // warmup groups (256 steps): 0.9^256 ~ 2e-12
#define YC     256           // t-chunk per fused u+y block

// ---------------- scratch (device globals; no allocation allowed) ----------------
// bit (t&31) of word [b][t>>5][h] = spike(b,t,h). 4 MB.
__device__ unsigned g_bits[B_SZ][NGRP][HID];
__device__ float    g_g[DMAX];          // impulse response C A^d B
__device__ float    g_y[B_SZ][SEQ];     // y[b][t]

// ---------------- LIF step: float-mask form (masks exactly 0.0/1.0) --------------
// w09 = rn(0.9 * v_pre-reset), ns = 1-spike_prev, act = (r<=0), r exact int.
// Every FFMA multiplies by exact 0/1 so rounding == reference's mul+add.
struct SnnState { float w09, ns, act, r; };

__device__ __forceinline__ void snn_step(SnnState& st, float xk,
                                         float& macc, float mc)
{
    float v1 = __fmaf_rn(st.w09, st.ns, xk);          // rn(0.9*v_post + x)
    float ge; asm("set.ge.f32.f32 %0, %1, %2;" : "=f"(ge) : "f"(v1), "f"(1.0f));
    float s  = __fmul_rn(ge, st.act);                 // spike as 0.0/1.0
    st.w09   = __fmul_rn(v1, 0.9f);
    st.ns    = __fmaf_rn(-ge, st.act, 1.0f);          // 1 - spike (exact)
    float rd = fmaxf(__fadd_rn(st.r, -1.0f), 0.0f);   // max(r-1,0), exact
    st.r     = __fmaf_rn(s, 5.0f, rd);                // spike => rd==0 => 5
    asm("set.le.f32.f32 %0, %1, %2;" : "=f"(st.act) : "f"(st.r), "f"(0.0f));
    macc     = __fmaf_rn(s, mc, macc);                // exact bit accumulation
}

// ---------------- pass 1: LIF neurons -> spike bitmasks (+hidden g block) --------
// 256 snn blocks of 128 threads: (b, hblk, chunk); each thread runs TWO adjacent
// (b,h) lanes (float2 loads = 2 independent chains of in-warp ILP).
// Last block computes g[d] = C A^d B concurrently.
__global__ void __launch_bounds__(128) snn_kernel(const float* __restrict__ x,
                                                  const float* __restrict__ Ap,
                                                  const float* __restrict__ Bp,
                                                  const float* __restrict__ Cp)
{
    __shared__ float As[64 * 65];
    __shared__ float ws[64];
    __shared__ float red[2];

    if (blockIdx.x >= B_SZ * 4 * CHUNKS) {
        // ---- g block: g[d] = C . (A^d B), d = 0..63 (tid<64 active) ----
        const int tid = threadIdx.x;
        for (int i = tid; i < 64 * 64; i += 128)
            As[(i >> 6) * 65 + (i & 63)] = Ap[i];
        float cv = 0.f, w = 0.f;
        if (tid < 64) { cv = Cp[tid]; w = Bp[tid]; ws[tid] = w; }
        __syncthreads();
        for (int d = 0; d < DMAX; d++) {
            if (tid < 64) {
                float p = cv * w;
                #pragma unroll
                for (int o = 16; o; o >>= 1) p += __shfl_down_sync(0xffffffffu, p, o);
                if ((tid & 31) == 0) red[tid >> 5] = p;
            }
            __syncthreads();
            if (tid == 0) g_g[d] = red[0] + red[1];
            if (d < DMAX - 1) {
                float wn = 0.f;
                if (tid < 64) {
                    float a0 = 0.f, a1 = 0.f, a2 = 0.f, a3 = 0.f;
                    #pragma unroll
                    for (int s = 0; s < 64; s += 4) {
                        a0 += As[tid * 65 + s + 0] * ws[s + 0];
                        a1 += As[tid * 65 + s + 1] * ws[s + 1];
                        a2 += As[tid * 65 + s + 2] * ws[s + 2];
                        a3 += As[tid * 65 + s + 3] * ws[s + 3];
                    }
                    wn = (a0 + a1) + (a2 + a3);
                }
                __syncthreads();
                if (tid < 64) ws[tid] = wn;
                __syncthreads();
                w = wn;
            }
        }
        return;
    }

    // ---- SNN path: 2 lanes per thread ----
    const int blk  = blockIdx.x;               // 0..255
    const int c    = blk & (CHUNKS - 1);
    const int hblk = (blk >> 3) & 3;
    const int b    = blk >> 5;
    const int tid  = threadIdx.x;
    const int h    = hblk * 256 + tid * 2;     // 2 consecutive hidden units

    const int warm    = (c == 0) ? 0 : WGRP;
    const int g0      = c * CGRP;
    const int tbegin  = g0 * 32 - warm * 32;
    const int ngroups = warm + CGRP;           // 16 or 24

    const float2* xp = (const float2*)(x + ((size_t)b * SEQ + tbegin) * HID + h);
    uint2* sbw = (uint2*)&g_bits[b][g0][h];
    const int HID2 = HID / 2;

    // 32-deep float2 buffer, constant indices only (no local-mem demotion);
    // value loaded at (gg,i) is consumed at (gg+1,i): 32-step prefetch distance.
    float2 buf[32];
    #pragma unroll
    for (int i = 0; i < 32; i++) buf[i] = xp[(size_t)i * HID2];
    const float2* xld = xp + (size_t)32 * HID2;

    SnnState s0 = {0,1,1,0}, s1 = {0,1,1,0};

    for (int gg = 0; gg < ngroups; gg++) {
        const bool pf = (gg + 1 < ngroups);
        float m0l = 0, m0h = 0, m1l = 0, m1h = 0;

        #pragma unroll
        for (int i = 0; i < 32; i++) {
            float2 xk = buf[i];
            if (pf) buf[i] = xld[(size_t)i * HID2];    // prefetch next group
            const float mc = (float)(1u << (i & 15));
            if (i < 16) {
                snn_step(s0, xk.x, m0l, mc);
                snn_step(s1, xk.y, m1l, mc);
            } else {
                snn_step(s0, xk.x, m0h, mc);
                snn_step(s1, xk.y, m1h, mc);
            }
        }
        xld += (size_t)32 * HID2;
        if (gg >= warm) {
            uint2 mv;
            mv.x = __float2uint_rn(m0l) | (__float2uint_rn(m0h) << 16);
            mv.y = __float2uint_rn(m1l) | (__float2uint_rn(m1h) << 16);
            *sbw = mv;                          // coalesced 8B store
            sbw += HID2;
        }
    }
}

// ---------------- pass 2: fused u (popcount transpose) + y (64-tap FIR) ----------
// grid: B_SZ*16 blocks, 256 threads; block (b,yc) produces y[b][yc*256 .. +256).
__global__ void __launch_bounds__(256) uy_kernel(const float* __restrict__ Dp)
{
    __shared__ unsigned wsm[HID];
    __shared__ int   part[8 * 32];
    __shared__ float u_s[64 + YC];   // u_s[i] = u[t0 - 64 + i]
    __shared__ float g_s[DMAX];

    const int b   = blockIdx.x >> 4;
    const int yc  = blockIdx.x & 15;
    const int t0  = yc * YC;
    const int gb  = yc * (YC / 32);
    const int tid = threadIdx.x;
    const int wid = tid >> 5, lane = tid & 31;

    if (tid < DMAX) g_s[tid] = g_g[tid];

    for (int j = -2; j < YC / 32; j++) {        // 2 halo groups + 8 own groups
        const int g  = gb + j;
        const int i0 = 64 + j * 32;
        if (g < 0) {
            if (tid < 32) u_s[i0 + tid] = 0.0f;
            continue;
        }
        ((uint4*)wsm)[tid] = ((const uint4*)&g_bits[b][g][0])[tid];
        __syncthreads();
        int cnt = 0;
        #pragma unroll 8
        for (int i2 = 0; i2 < 128; i2++)
            cnt += (int)((wsm[wid * 128 + i2] >> lane) & 1u);
        part[wid * 32 + lane] = cnt;
        __syncthreads();
        if (tid < 32) {
            int tot = 0;
            #pragma unroll
            for (int ww = 0; ww < 8; ww++) tot += part[ww * 32 + tid];
            u_s[i0 + tid] = (float)tot * (1.0f / (float)HID);
        }
        __syncthreads();
    }

    const float Ds = *Dp;
    {
        const int i = tid;                      // YC == blockDim.x
        float acc = Ds * u_s[64 + i];
        #pragma unroll
        for (int d = 0; d < DMAX; d++)
            acc += g_s[d] * u_s[64 + i - d];
        g_y[b][t0 + i] = acc;
    }
}

// ---------------- pass 3: out[b][t][h] = spike_bit + y[b][t] ---------------------
// grid: B_SZ * NGRP * 2 blocks; block covers 16 t x 1024 h (64 KB of output).
__global__ void __launch_bounds__(256) out_kernel(float4* __restrict__ out)
{
    __shared__ float ys[16], ys1[16];

    const int blk  = blockIdx.x;
    const int half = blk & 1;
    const int g    = (blk >> 1) & (NGRP - 1);
    const int b    = blk >> 8;
    const int tid  = threadIdx.x;            // h4 = tid: hidden 4*tid..4*tid+3

    if (tid < 16) {
        float yv = g_y[b][g * 32 + half * 16 + tid];
        ys[tid]  = yv;
        ys1[tid] = yv + 1.0f;
    }
    const uint4 wv = ((const uint4*)&g_bits[b][g][0])[tid];
    __syncthreads();

    float4* base = out + ((size_t)(b * SEQ + g * 32 + half * 16) * HID) / 4 + tid;
    #pragma unroll
    for (int t = 0; t < 16; t++) {
        const unsigned bit = 1u << (half * 16 + t);
        const float y  = ys[t];
        const float y1 = ys1[t];
        float4 o;
        o.x = (wv.x & bit) ? y1 : y;
        o.y = (wv.y & bit) ? y1 : y;
        o.z = (wv.z & bit) ? y1 : y;
        o.w = (wv.w & bit) ? y1 : y;
        __stcs(&base[(size_t)t * (HID / 4)], o);
    }
}

// ---------------- launch ----------------------------------------------------------
extern "C" void kernel_launch(void* const* d_in, const int* in_sizes, int n_in,
                              void* d_out, int out_size)
{
    const float* x  = (const float*)d_in[0];   // (8, 4096, 1024) f32
    const float* A  = (const float*)d_in[1];   // (64, 64)
    const float* Bv = (const float*)d_in[2];   // (64, 1)
    const float* Cv = (const float*)d_in[3];   // (1, 64)
    const float* Dp = (const float*)d_in[4];   // (1, 1)

    snn_kernel<<<B_SZ * 4 * CHUNKS + 1, 128>>>(x, A, Bv, Cv);
    uy_kernel<<<B_SZ * 16, 256>>>(Dp);
    out_kernel<<<B_SZ * NGRP * 2, 256>>>((float4*)d_out);
}